// round 1
// baseline (speedup 1.0000x reference)
#include <cuda_runtime.h>
#include <math.h>

#define T_FRAMES   3000
#define F_BINS     201
#define BATCH      32
#define CHUNK      300
#define CHUNKS     (T_FRAMES / CHUNK)   // 10
#define HALO       60                   // >= 40 needed; 60 keeps mod-30 alignment
#define NTHREADS   224
#define NWARPS     (NTHREADS / 32)
#define EPS_F      1e-5f
#define INV_LN10   0.43429448190325176f

// One step of the scan. J must be a compile-time constant (unrolled loops) so
// the ring buffers stay in registers. DO_SUB=false for the first 30 frames of a
// block's scan (ring holds zeros; sum_lw must not subtract log(0+eps)).
#define STEP(J, TT, RC10, RC30, DO_SUB, EMIT)                                    \
  do {                                                                           \
    const int t_ = (TT);                                                         \
    float2 xv = make_float2(0.f, 0.f);                                           \
    if (active) xv = *(const float2*)xp;                                         \
    xp += F_BINS * 2;                                                            \
    const float s_t = (xv.x * xv.x + xv.y * xv.y) * Cf;                          \
    const float welch_t = (t_ == 0) ? 0.f : sum_s * (RC10);                      \
    const float lw_t = __logf(welch_t + EPS_F);                                  \
    if (EMIT) {                                                                  \
      float contrib = 0.f;                                                       \
      if (active && t_ > 0) {                                                    \
        const float am  = fmaf(sum_w, (RC30), EPS_F);                            \
        const float mlw = sum_lw * (RC30);                                       \
        contrib = (__logf(am) - mlw) * INV_LN10;                                 \
      }                                                                          \
      _Pragma("unroll")                                                          \
      for (int off_ = 16; off_ > 0; off_ >>= 1)                                  \
        contrib += __shfl_xor_sync(0xffffffffu, contrib, off_);                  \
      if (lane == 0) partials[warp][t_ - chunk_start] = contrib;                 \
    }                                                                            \
    if (DO_SUB) {                                                                \
      const float w_old = ring_w[(J) % 30];                                      \
      sum_w  += welch_t - w_old;                                                 \
      sum_lw += lw_t - __logf(w_old + EPS_F);                                    \
    } else {                                                                     \
      sum_w  += welch_t;                                                         \
      sum_lw += lw_t;                                                            \
    }                                                                            \
    ring_w[(J) % 30] = welch_t;                                                  \
    sum_s += s_t - ring_s[(J) % 10];                                             \
    ring_s[(J) % 10] = s_t;                                                      \
  } while (0)

__global__ __launch_bounds__(NTHREADS, 3)
void ltsf_kernel(const float* __restrict__ x, float* __restrict__ out,
                 const float cA) {
  const int unit = blockIdx.x;
  const int b = unit / CHUNKS;
  const int c = unit % CHUNKS;
  const int chunk_start = c * CHUNK;
  const int t_begin = (c == 0) ? 0 : (chunk_start - HALO);

  const int tid  = threadIdx.x;
  const int f    = tid;
  const bool active = (f < F_BINS);
  const int lane = tid & 31;
  const int warp = tid >> 5;

  __shared__ float partials[NWARPS][CHUNK];

  // per-bin scale: interior bins doubled (welch one-sided spectrum)
  const float Cf = (f == 0 || f == F_BINS - 1) ? cA : 2.0f * cA;

  const float* xp =
      x + ((size_t)b * T_FRAMES + (size_t)t_begin) * (F_BINS * 2) +
      (active ? f : 0) * 2;

  // register-resident ring buffers (all indices compile-time via full unroll)
  float ring_s[10];
  float ring_w[30];
  float sum_s = 0.f, sum_w = 0.f, sum_lw = 0.f;
#pragma unroll
  for (int i = 0; i < 10; i++) ring_s[i] = 0.f;
#pragma unroll
  for (int i = 0; i < 30; i++) ring_w[i] = 0.f;

  // ---- warm-up block: first 30 frames of the scan, no ring subtraction ----
  // For c==0 these are real frames (emit, with exact ramp-up counts: the
  // compile-time j IS the absolute t). For c>0 these are halo frames (no emit;
  // rc values only shape garbage that gets evicted before emission starts).
  {
    const bool emit0 = (c == 0);
#pragma unroll
    for (int j = 0; j < 30; j++) {
      const int cj10 = (j < 1) ? 1 : (j > 10 ? 10 : j);
      const int cj30 = (j < 1) ? 1 : j;
      const float rc10 = 1.0f / (float)cj10;
      const float rc30 = 1.0f / (float)cj30;
      STEP(j, t_begin + j, rc10, rc30, false, emit0);
    }
  }

  // ---- steady blocks: t >= 30 everywhere, counts are constant 10 / 30 ----
  for (int tb = t_begin + 30; tb < chunk_start + CHUNK; tb += 30) {
    const bool emit = (tb >= chunk_start);
#pragma unroll
    for (int j = 0; j < 30; j++) {
      STEP(j, tb + j, 0.1f, (1.0f / 30.0f), true, emit);
    }
  }

  // ---- combine per-warp partials, write output ----
  __syncthreads();
  for (int i = tid; i < CHUNK; i += NTHREADS) {
    float v = 0.f;
#pragma unroll
    for (int w = 0; w < NWARPS; w++) v += partials[w][i];
    out[(size_t)b * T_FRAMES + chunk_start + i] = v;
  }
}

extern "C" void kernel_launch(void* const* d_in, const int* in_sizes, int n_in,
                              void* d_out, int out_size) {
  (void)in_sizes; (void)n_in; (void)out_size;
  // hamming_sq_sum(25), periodic: sum((0.54 - 0.46*cos(2*pi*k/25))^2)
  double h = 0.0;
  for (int k = 0; k < 25; k++) {
    double w = 0.54 - 0.46 * cos(2.0 * M_PI * (double)k / 25.0);
    h += w * w;
  }
  // fold the /M (spectr) and /SAMPLE_RATE (welch) into one per-bin constant
  const float cA = (float)(h / 16000.0 / 10.0);

  const float* x = (const float*)d_in[0];
  float* out = (float*)d_out;
  ltsf_kernel<<<BATCH * CHUNKS, NTHREADS>>>(x, out, cA);
}

// round 2
// speedup vs baseline: 1.0790x; 1.0790x over previous
#include <cuda_runtime.h>
#include <math.h>

#define T_FRAMES   3000
#define F_BINS     201
#define BATCH      32
#define CHUNK      300
#define CHUNKS     (T_FRAMES / CHUNK)   // 10
#define HALO       60                   // >= 40 needed; 60 keeps mod-30 alignment
#define NTHREADS   224
#define NWARPS     (NTHREADS / 32)
#define EPS_F      1e-5f
#define INV_LN10   0.43429448190325176f

// One scan step. J compile-time so rings stay in registers. No warp
// communication here: contrib goes to smem (fire-and-forget STS), reduction
// is batched per 30-frame group. DO_SUB=false during ring warm-up.
#define STEP(J, TT, RC10, RC30, DO_SUB, EMIT)                                    \
  do {                                                                           \
    const int t_ = (TT);                                                         \
    float2 xv = make_float2(0.f, 0.f);                                           \
    if (active) xv = *(const float2*)xp;                                         \
    xp += F_BINS * 2;                                                            \
    const float s_t = (xv.x * xv.x + xv.y * xv.y) * Cf;                          \
    const float welch_t = (t_ == 0) ? 0.f : sum_s * (RC10);                      \
    const float lw_t = __logf(welch_t + EPS_F);                                  \
    if (EMIT) {                                                                  \
      float contrib = 0.f;                                                       \
      if (active && t_ > 0) {                                                    \
        const float am  = fmaf(sum_w, (RC30), EPS_F);                            \
        const float mlw = sum_lw * (RC30);                                       \
        contrib = (__logf(am) - mlw) * INV_LN10;                                 \
      }                                                                          \
      buf[J][tid] = contrib;                                                     \
    }                                                                            \
    if (DO_SUB) {                                                                \
      const float w_old = ring_w[(J) % 30];                                      \
      sum_w  += welch_t - w_old;                                                 \
      sum_lw += lw_t - __logf(w_old + EPS_F);                                    \
    } else {                                                                     \
      sum_w  += welch_t;                                                         \
      sum_lw += lw_t;                                                            \
    }                                                                            \
    ring_w[(J) % 30] = welch_t;                                                  \
    sum_s += s_t - ring_s[(J) % 10];                                             \
    ring_s[(J) % 10] = s_t;                                                      \
  } while (0)

// Batched cross-thread reduction of one 30-frame group. Uniform control flow
// across the block (caller guarantees `emit` is block-uniform).
#define REDUCE_GROUP(TB)                                                         \
  do {                                                                           \
    __syncthreads();                                                             \
    for (int j_ = warp; j_ < 30; j_ += NWARPS) {                                 \
      float v_ = 0.f;                                                            \
      _Pragma("unroll")                                                          \
      for (int i_ = 0; i_ < NTHREADS / 32; i_++)                                 \
        v_ += buf[j_][lane + 32 * i_];                                           \
      _Pragma("unroll")                                                          \
      for (int off_ = 16; off_ > 0; off_ >>= 1)                                  \
        v_ += __shfl_xor_sync(0xffffffffu, v_, off_);                            \
      if (lane == 0) out[(size_t)b * T_FRAMES + (TB) + j_] = v_;                 \
    }                                                                            \
    __syncthreads();                                                             \
  } while (0)

__global__ __launch_bounds__(NTHREADS, 3)
void ltsf_kernel(const float* __restrict__ x, float* __restrict__ out,
                 const float cA) {
  const int unit = blockIdx.x;
  const int b = unit / CHUNKS;
  const int c = unit % CHUNKS;
  const int chunk_start = c * CHUNK;
  const int t_begin = (c == 0) ? 0 : (chunk_start - HALO);

  const int tid  = threadIdx.x;
  const int f    = tid;
  const bool active = (f < F_BINS);
  const int lane = tid & 31;
  const int warp = tid >> 5;

  __shared__ float buf[30][NTHREADS];   // per-group contrib tile (26.9 KB)

  // per-bin scale: interior bins doubled (welch one-sided spectrum)
  const float Cf = (f == 0 || f == F_BINS - 1) ? cA : 2.0f * cA;

  const float* xp =
      x + ((size_t)b * T_FRAMES + (size_t)t_begin) * (F_BINS * 2) +
      (active ? f : 0) * 2;

  // register-resident ring buffers (indices compile-time via full unroll)
  float ring_s[10];
  float ring_w[30];
  float sum_s = 0.f, sum_w = 0.f, sum_lw = 0.f;
#pragma unroll
  for (int i = 0; i < 10; i++) ring_s[i] = 0.f;
#pragma unroll
  for (int i = 0; i < 30; i++) ring_w[i] = 0.f;

  // ---- warm-up group: first 30 frames of the scan, no ring subtraction ----
  // c==0: real frames with exact ramp-up divisors (compile-time j == t).
  // c>0: halo frames; values stabilize before emission (HALO=60 > 40).
  {
    const bool emit0 = (c == 0);
#pragma unroll
    for (int j = 0; j < 30; j++) {
      const int cj10 = (j < 1) ? 1 : (j > 10 ? 10 : j);
      const int cj30 = (j < 1) ? 1 : j;
      const float rc10 = 1.0f / (float)cj10;
      const float rc30 = 1.0f / (float)cj30;
      STEP(j, t_begin + j, rc10, rc30, false, emit0);
    }
    if (emit0) REDUCE_GROUP(t_begin);
  }

  // ---- steady groups: counts are constant 10 / 30 ----
  for (int tb = t_begin + 30; tb < chunk_start + CHUNK; tb += 30) {
    const bool emit = (tb >= chunk_start);   // block-uniform
#pragma unroll
    for (int j = 0; j < 30; j++) {
      STEP(j, tb + j, 0.1f, (1.0f / 30.0f), true, emit);
    }
    if (emit) REDUCE_GROUP(tb);
  }
}

extern "C" void kernel_launch(void* const* d_in, const int* in_sizes, int n_in,
                              void* d_out, int out_size) {
  (void)in_sizes; (void)n_in; (void)out_size;
  // hamming_sq_sum(25), periodic: sum((0.54 - 0.46*cos(2*pi*k/25))^2)
  double h = 0.0;
  for (int k = 0; k < 25; k++) {
    double w = 0.54 - 0.46 * cos(2.0 * M_PI * (double)k / 25.0);
    h += w * w;
  }
  // fold the /M (spectr) and /SAMPLE_RATE (welch) into one per-bin constant
  const float cA = (float)(h / 16000.0 / 10.0);

  const float* x = (const float*)d_in[0];
  float* out = (float*)d_out;
  ltsf_kernel<<<BATCH * CHUNKS, NTHREADS>>>(x, out, cA);
}

// round 5
// speedup vs baseline: 2.5777x; 2.3889x over previous
#include <cuda_runtime.h>
#include <stdint.h>
#include <math.h>

#define T_FRAMES   3000
#define F_BINS     201
#define FSTRIDE    (F_BINS * 2)         // floats per frame
#define BATCH      32
#define CHUNK      200
#define CHUNKS     (T_FRAMES / CHUNK)   // 15
#define HALO       60                   // >= 40 needed; 60 keeps warm-up mod-30
#define NTHREADS   224
#define NWARPS     (NTHREADS / 32)
#define EPS_F      1e-5f
#define INV_LN10   0.43429448190325176f
#define PIPE_DEPTH 8                    // cp.async groups in flight
#define NSLOTS     10                   // smem ring slots (30 % 10 == 0)

__device__ __forceinline__ void cp_async8(uint32_t smem_addr, const float* gptr) {
  asm volatile("cp.async.ca.shared.global [%0], [%1], 8;\n"
               :: "r"(smem_addr), "l"(gptr));
}
#define CP_COMMIT() asm volatile("cp.async.commit_group;\n" ::: "memory")
#define CP_WAIT7()  asm volatile("cp.async.wait_group 7;\n" ::: "memory")

// One scan step. J compile-time (unrolled) so rings stay in registers and the
// smem slot index is an immediate. Data comes from the cp.async smem ring;
// each thread reads/writes only its own slot column -> no cross-thread sync.
#define STEP(J, TT, RC10, RC30, DO_SUB, EMIT)                                    \
  do {                                                                           \
    const int t_ = (TT);                                                         \
    CP_WAIT7();                                                                  \
    float2 xv = stage[(J) % NSLOTS][tid];                                        \
    {                                                                            \
      const int tp_ = min(t_ + PIPE_DEPTH, T_FRAMES - 1);                        \
      cp_async8(slot0 + (((J) + PIPE_DEPTH) % NSLOTS) * (NTHREADS * 8),          \
                xbase + (size_t)tp_ * FSTRIDE);                                  \
    }                                                                            \
    CP_COMMIT();                                                                 \
    const float s_t = (xv.x * xv.x + xv.y * xv.y) * Cf;                          \
    const float welch_t = (t_ == 0) ? 0.f : sum_s * (RC10);                      \
    const float lw_t = __logf(welch_t + EPS_F);                                  \
    if (EMIT) {                                                                  \
      float contrib = 0.f;                                                       \
      if (active && t_ > 0) {                                                    \
        const float am  = fmaf(sum_w, (RC30), EPS_F);                            \
        const float mlw = sum_lw * (RC30);                                       \
        contrib = (__logf(am) - mlw) * INV_LN10;                                 \
      }                                                                          \
      buf[J][tid] = contrib;                                                     \
    }                                                                            \
    if (DO_SUB) {                                                                \
      const float w_old = ring_w[(J) % 30];                                      \
      sum_w  += welch_t - w_old;                                                 \
      sum_lw += lw_t - __logf(w_old + EPS_F);                                    \
    } else {                                                                     \
      sum_w  += welch_t;                                                         \
      sum_lw += lw_t;                                                            \
    }                                                                            \
    ring_w[(J) % 30] = welch_t;                                                  \
    sum_s += s_t - ring_s[(J) % 10];                                             \
    ring_s[(J) % 10] = s_t;                                                      \
  } while (0)

// Batched cross-thread reduction of one 30-frame group (block-uniform emit).
// Frames past the chunk boundary are computed but NOT written (the next chunk
// owns them) -- CHUNK need not be a multiple of 30.
#define REDUCE_GROUP(TB)                                                         \
  do {                                                                           \
    __syncthreads();                                                             \
    for (int j_ = warp; j_ < 30; j_ += NWARPS) {                                 \
      float v_ = 0.f;                                                            \
      _Pragma("unroll")                                                          \
      for (int i_ = 0; i_ < NTHREADS / 32; i_++)                                 \
        v_ += buf[j_][lane + 32 * i_];                                           \
      _Pragma("unroll")                                                          \
      for (int off_ = 16; off_ > 0; off_ >>= 1)                                  \
        v_ += __shfl_xor_sync(0xffffffffu, v_, off_);                            \
      if (lane == 0 && (TB) + j_ < chunk_end)                                    \
        out[(size_t)b * T_FRAMES + (TB) + j_] = v_;                              \
    }                                                                            \
    __syncthreads();                                                             \
  } while (0)

__global__ __launch_bounds__(NTHREADS, 4)
void ltsf_kernel(const float* __restrict__ x, float* __restrict__ out,
                 const float cA) {
  const int unit = blockIdx.x;
  const int b = unit / CHUNKS;
  const int c = unit % CHUNKS;
  const int chunk_start = c * CHUNK;
  const int chunk_end = chunk_start + CHUNK;
  const int t_begin = (c == 0) ? 0 : (chunk_start - HALO);

  const int tid  = threadIdx.x;
  const int f    = tid;
  const bool active = (f < F_BINS);
  const int lane = tid & 31;
  const int warp = tid >> 5;

  __shared__ float2 stage[NSLOTS][NTHREADS];  // cp.async ring (17.9 KB)
  __shared__ float  buf[30][NTHREADS];        // contrib tile (26.9 KB)

  // per-bin scale: interior bins doubled (welch one-sided spectrum)
  const float Cf = (f == 0 || f == F_BINS - 1) ? cA : 2.0f * cA;

  // inactive threads stream bin 0 (harmless; contrib is masked)
  const int fsel = active ? f : 0;
  const float* xbase =
      x + (size_t)b * T_FRAMES * FSTRIDE + (size_t)fsel * 2;
  const uint32_t slot0 = (uint32_t)__cvta_generic_to_shared(&stage[0][tid]);

  // register-resident ring buffers (indices compile-time via full unroll)
  float ring_s[10];
  float ring_w[30];
  float sum_s = 0.f, sum_w = 0.f, sum_lw = 0.f;
#pragma unroll
  for (int i = 0; i < 10; i++) ring_s[i] = 0.f;
#pragma unroll
  for (int i = 0; i < 30; i++) ring_w[i] = 0.f;

  // ---- pipeline prologue: frames q=0..PIPE_DEPTH-1 ----
#pragma unroll
  for (int p = 0; p < PIPE_DEPTH; p++) {
    cp_async8(slot0 + (p % NSLOTS) * (NTHREADS * 8),
              xbase + (size_t)(t_begin + p) * FSTRIDE);
    CP_COMMIT();
  }

  // ---- warm-up group: first 30 frames of the scan, no ring subtraction ----
  // c==0: real frames with exact ramp-up divisors (compile-time j == t).
  // c>0: halo frames; state stabilizes before emission (HALO=60 > 40).
  {
    const bool emit0 = (c == 0);
#pragma unroll
    for (int j = 0; j < 30; j++) {
      const int cj10 = (j < 1) ? 1 : (j > 10 ? 10 : j);
      const int cj30 = (j < 1) ? 1 : j;
      const float rc10 = 1.0f / (float)cj10;
      const float rc30 = 1.0f / (float)cj30;
      STEP(j, t_begin + j, rc10, rc30, false, emit0);
    }
    if (emit0) REDUCE_GROUP(t_begin);
  }

  // ---- steady groups: counts are constant 10 / 30 ----
  for (int tb = t_begin + 30; tb < chunk_end; tb += 30) {
    const bool emit = (tb + 29 >= chunk_start);  // block-uniform
#pragma unroll
    for (int j = 0; j < 30; j++) {
      STEP(j, tb + j, 0.1f, (1.0f / 30.0f), true, emit);
    }
    if (emit) REDUCE_GROUP(tb);
  }
}

extern "C" void kernel_launch(void* const* d_in, const int* in_sizes, int n_in,
                              void* d_out, int out_size) {
  (void)in_sizes; (void)n_in; (void)out_size;
  // hamming_sq_sum(25), periodic: sum((0.54 - 0.46*cos(2*pi*k/25))^2)
  double h = 0.0;
  for (int k = 0; k < 25; k++) {
    double w = 0.54 - 0.46 * cos(2.0 * M_PI * (double)k / 25.0);
    h += w * w;
  }
  // fold the /M (spectr) and /SAMPLE_RATE (welch) into one per-bin constant
  const float cA = (float)(h / 16000.0 / 10.0);

  const float* x = (const float*)d_in[0];
  float* out = (float*)d_out;
  ltsf_kernel<<<BATCH * CHUNKS, NTHREADS>>>(x, out, cA);
}